// round 2
// baseline (speedup 1.0000x reference)
#include <cuda_runtime.h>
#include <stdint.h>
#include <stddef.h>

// ---------------- problem constants ----------------
#define B_    2
#define NQ_   768
#define NK_   768
#define DMSG_ 32

// ---------------- static scratch (no allocations allowed) ----------------
__device__ float g_qe[B_ * NQ_ * 3 * DMSG_];   // [b,q,c,m] projected equi (+bias)
__device__ float g_ke[B_ * NK_ * 3 * DMSG_];
__device__ float g_Aq[B_ * NQ_ * 128];         // b1 + qi @ W1[0:32,:]
__device__ float g_Bk[B_ * NK_ * 128];         //      ki @ W1[32:64,:]

// ---------------- helpers ----------------
__device__ __forceinline__ float tf32r(float x) {
    uint32_t u;
    asm("cvt.rna.tf32.f32 %0, %1;" : "=r"(u) : "f"(x));
    return __uint_as_float(u);
}
__device__ __forceinline__ uint32_t U(float x) { return __float_as_uint(x); }

__device__ __forceinline__ void mma_tf32(float* d, const uint32_t* a, const uint32_t* b) {
    asm volatile(
        "mma.sync.aligned.m16n8k8.row.col.f32.tf32.tf32.f32 "
        "{%0,%1,%2,%3}, {%4,%5,%6,%7}, {%8,%9}, {%0,%1,%2,%3};"
        : "+f"(d[0]), "+f"(d[1]), "+f"(d[2]), "+f"(d[3])
        : "r"(a[0]), "r"(a[1]), "r"(a[2]), "r"(a[3]), "r"(b[0]), "r"(b[1]));
}

// =====================================================================
// Kernel P: per-row projections.
//   side 0: row in q-space, side 1: row in k-space. 128 threads per row.
// =====================================================================
__global__ __launch_bounds__(128)
void proj_kernel(const float* __restrict__ q_equi, const float* __restrict__ q_inv,
                 const float* __restrict__ k_equi, const float* __restrict__ k_inv,
                 const float* __restrict__ Wqi, const float* __restrict__ bqi,
                 const float* __restrict__ Wki, const float* __restrict__ bki,
                 const float* __restrict__ Wqe, const float* __restrict__ bqe,
                 const float* __restrict__ Wke, const float* __restrict__ bke,
                 const float* __restrict__ W1,  const float* __restrict__ b1)
{
    const int side = blockIdx.y;          // 0 = q, 1 = k
    const int r    = blockIdx.x;          // b*768 + n
    const int tid  = threadIdx.x;

    const float* xe = side ? k_equi : q_equi;
    const float* xi = side ? k_inv  : q_inv;
    const float* We = side ? Wke : Wqe;
    const float* be = side ? bke : bqe;
    const float* Wi = side ? Wki : Wqi;
    const float* bi = side ? bki : bqi;
    float* oute = side ? g_ke : g_qe;
    float* outA = side ? g_Bk : g_Aq;

    __shared__ float sxe[768];
    __shared__ float sxi[256];
    __shared__ float spi[32];

    for (int i = tid; i < 768; i += 128) sxe[i] = xe[(size_t)r * 768 + i];
    for (int i = tid; i < 256; i += 128) sxi[i] = xi[(size_t)r * 256 + i];
    __syncthreads();

    if (tid < 96) {                        // warps 0..2 : equivariant projection
        const int c = tid >> 5, m = tid & 31;
        float acc = be[m];
        #pragma unroll 4
        for (int d = 0; d < 256; d++)
            acc = fmaf(sxe[c * 256 + d], We[d * 32 + m], acc);
        oute[(size_t)r * 96 + c * 32 + m] = acc;
    } else {                               // warp 3 : invariant projection
        const int m = tid - 96;
        float acc = bi[m];
        #pragma unroll 4
        for (int d = 0; d < 256; d++)
            acc = fmaf(sxi[d], Wi[d * 32 + m], acc);
        spi[m] = acc;
    }
    __syncthreads();

    // Aq / Bk : 128 outputs, one per thread
    {
        float acc = side ? 0.0f : b1[tid];
        const int ro = side ? 32 : 0;
        #pragma unroll
        for (int m = 0; m < 32; m++)
            acc = fmaf(spi[m], W1[(ro + m) * 128 + tid], acc);
        outA[(size_t)r * 128 + tid] = acc;
    }
}

// =====================================================================
// Kernel B: pairwise tile kernel.
//   CTA = 2 q-rows x 64 k-rows = 128 pairs. 256 threads (8 warps).
//   GEMM1: feats[128x64] @ W1cd[64x128]  (tf32 mma.sync)
//   epilogue: +Aq +Bk (fp32 exact), silu
//   GEMM2: h[128x128] @ W2[128x64] + b2
// =====================================================================
// SMEM layout (floats):
#define LDW1 132
#define LDF   68
#define LDH  132
#define LDW2  68
#define LDBK  66
#define O_W1 0                 // [64][132]   = 8448
#define O_F  8448              // [128][68]   = 8704
#define O_H  17152             // [128][132]  = 16896
#define O_W2 34048             // [128][68]   = 8704  (aliased with sKE [64][96])
#define O_BK 42752             // [128][66]   = 8448  (Bk transposed: [f][kk])
#define O_AQ 51200             // [2][128]
#define O_QE 51456             // [2][96]
#define O_B2 51648             // [64]
#define SMEM_FLOATS 51712
#define SMEM_BYTES  (SMEM_FLOATS * 4)

__global__ __launch_bounds__(256, 1)
void pair_kernel(const float* __restrict__ W1, const float* __restrict__ W2,
                 const float* __restrict__ b2, float* __restrict__ out)
{
    extern __shared__ float sm[];
    float* sW1 = sm + O_W1;
    float* sF  = sm + O_F;
    float* sH  = sm + O_H;
    float* sW2 = sm + O_W2;
    float* sKE = sm + O_W2;    // alias: ke tile lives here until feats done
    float* sBK = sm + O_BK;
    float* sAQ = sm + O_AQ;
    float* sQE = sm + O_QE;
    float* sB2 = sm + O_B2;

    const int tid = threadIdx.x;
    const int b   = blockIdx.z;
    const int k0  = blockIdx.x * 64;
    const int q0  = blockIdx.y * 2;

    // ---------------- phase 1: loads ----------------
    for (int i = tid; i < 64 * 128; i += 256) {         // W1 rows 64..127 (dot|dist block)
        const int r = i >> 7, f = i & 127;
        sW1[r * LDW1 + f] = tf32r(W1[(64 + r) * 128 + f]);
    }
    for (int i = tid; i < 64 * 96; i += 256)            // ke tile (contiguous rows)
        sKE[i] = g_ke[(size_t)(b * NK_ + k0) * 96 + i];
    if (tid < 192)                                      // qe tile (2 rows)
        sQE[tid] = g_qe[(size_t)(b * NQ_ + q0) * 96 + tid];
    sAQ[tid] = g_Aq[(size_t)(b * NQ_ + q0) * 128 + tid];  // 2 rows = 256 floats
    for (int i = tid; i < 64 * 128; i += 256) {         // Bk tile, stored transposed
        const int kk = i >> 7, f = i & 127;
        sBK[f * LDBK + kk] = g_Bk[(size_t)(b * NK_ + k0) * 128 + i];
    }
    if (tid < 64) sB2[tid] = b2[tid];
    __syncthreads();

    // ---------------- phase 2: feats (dot + dist), tf32-rounded ----------------
    #pragma unroll
    for (int it = 0; it < 4; it++) {
        const int g  = tid + it * 256;     // 1024 groups of 4 m-channels
        const int p  = g >> 3;             // pair 0..127
        const int m  = (g & 7) * 4;
        const int qq = p >> 6, kk = p & 63;
        float4 dot = make_float4(0.f, 0.f, 0.f, 0.f);
        float4 d2  = make_float4(0.f, 0.f, 0.f, 0.f);
        #pragma unroll
        for (int c = 0; c < 3; c++) {
            const float4 a  = *(const float4*)&sQE[qq * 96 + c * 32 + m];
            const float4 bb = *(const float4*)&sKE[kk * 96 + c * 32 + m];
            dot.x = fmaf(a.x, bb.x, dot.x);
            dot.y = fmaf(a.y, bb.y, dot.y);
            dot.z = fmaf(a.z, bb.z, dot.z);
            dot.w = fmaf(a.w, bb.w, dot.w);
            float dx = a.x - bb.x; d2.x = fmaf(dx, dx, d2.x);
            float dy = a.y - bb.y; d2.y = fmaf(dy, dy, d2.y);
            float dz = a.z - bb.z; d2.z = fmaf(dz, dz, d2.z);
            float dw = a.w - bb.w; d2.w = fmaf(dw, dw, d2.w);
        }
        float4 o1 = make_float4(tf32r(dot.x), tf32r(dot.y), tf32r(dot.z), tf32r(dot.w));
        float4 o2 = make_float4(tf32r(sqrtf(d2.x)), tf32r(sqrtf(d2.y)),
                                tf32r(sqrtf(d2.z)), tf32r(sqrtf(d2.w)));
        *(float4*)&sF[p * LDF + m]      = o1;
        *(float4*)&sF[p * LDF + 32 + m] = o2;
    }
    __syncthreads();    // feats done; ke no longer needed

    // load W2 into the region previously holding ke (read first at GEMM2, after next sync)
    for (int i = tid; i < 128 * 64; i += 256) {
        const int r = i >> 6, f = i & 63;
        sW2[r * LDW2 + f] = tf32r(W2[i]);
    }

    // ---------------- phase 3: GEMM1 (M=128, N=128, K=64) ----------------
    const int wid = tid >> 5, lane = tid & 31;
    const int grp = lane >> 2, tig = lane & 3;
    const int wm = wid & 3, wn = wid >> 2;     // warps 4(M) x 2(N)
    const int mb = wm * 32, nb = wn * 64;      // warp tile 32 x 64

    float c1[2][8][4];
    #pragma unroll
    for (int mt = 0; mt < 2; mt++)
        #pragma unroll
        for (int nt = 0; nt < 8; nt++)
            #pragma unroll
            for (int j = 0; j < 4; j++) c1[mt][nt][j] = 0.f;

    #pragma unroll
    for (int ks = 0; ks < 8; ks++) {
        const int kc = ks * 8;
        uint32_t a[2][4];
        #pragma unroll
        for (int mt = 0; mt < 2; mt++) {
            const int r = mb + mt * 16 + grp;
            a[mt][0] = U(sF[r * LDF + kc + tig]);
            a[mt][1] = U(sF[(r + 8) * LDF + kc + tig]);
            a[mt][2] = U(sF[r * LDF + kc + tig + 4]);
            a[mt][3] = U(sF[(r + 8) * LDF + kc + tig + 4]);
        }
        #pragma unroll
        for (int nt = 0; nt < 8; nt++) {
            uint32_t bf[2];
            const int cn = nb + nt * 8 + grp;
            bf[0] = U(sW1[(kc + tig) * LDW1 + cn]);
            bf[1] = U(sW1[(kc + tig + 4) * LDW1 + cn]);
            #pragma unroll
            for (int mt = 0; mt < 2; mt++)
                mma_tf32(c1[mt][nt], a[mt], bf);
        }
    }

    // ---------------- epilogue 1: +Aq +Bk (fp32), silu, -> sH (tf32) ----------------
    {
        const int qq = mb >> 6;        // constant per warp (rows 0..63 -> q0, 64..127 -> q0+1)
        #pragma unroll
        for (int nt = 0; nt < 8; nt++) {
            #pragma unroll
            for (int j = 0; j < 2; j++) {
                const int f  = nb + nt * 8 + tig * 2 + j;
                const float aq = sAQ[qq * 128 + f];
                #pragma unroll
                for (int mt = 0; mt < 2; mt++) {
                    #pragma unroll
                    for (int h = 0; h < 2; h++) {
                        const int r  = mb + mt * 16 + grp + h * 8;
                        const int kk = r & 63;
                        const float v = c1[mt][nt][h * 2 + j] + aq + sBK[f * LDBK + kk];
                        const float e = __expf(-v);
                        const float hh = __fdividef(v, 1.0f + e);
                        sH[r * LDH + f] = tf32r(hh);
                    }
                }
            }
        }
    }
    __syncthreads();    // sH complete (also orders sW2 load before GEMM2 reads)

    // ---------------- phase 4: GEMM2 (M=128, N=64, K=128) ----------------
    const int nb2 = wn * 32;                   // warps 4(M) x 2(N), warp tile 32 x 32
    float c2[2][4][4];
    #pragma unroll
    for (int mt = 0; mt < 2; mt++)
        #pragma unroll
        for (int nt = 0; nt < 4; nt++)
            #pragma unroll
            for (int j = 0; j < 4; j++) c2[mt][nt][j] = 0.f;

    #pragma unroll
    for (int ks = 0; ks < 16; ks++) {
        const int kc = ks * 8;
        uint32_t a[2][4];
        #pragma unroll
        for (int mt = 0; mt < 2; mt++) {
            const int r = mb + mt * 16 + grp;
            a[mt][0] = U(sH[r * LDH + kc + tig]);
            a[mt][1] = U(sH[(r + 8) * LDH + kc + tig]);
            a[mt][2] = U(sH[r * LDH + kc + tig + 4]);
            a[mt][3] = U(sH[(r + 8) * LDH + kc + tig + 4]);
        }
        #pragma unroll
        for (int nt = 0; nt < 4; nt++) {
            uint32_t bf[2];
            const int cn = nb2 + nt * 8 + grp;
            bf[0] = U(sW2[(kc + tig) * LDW2 + cn]);
            bf[1] = U(sW2[(kc + tig + 4) * LDW2 + cn]);
            #pragma unroll
            for (int mt = 0; mt < 2; mt++)
                mma_tf32(c2[mt][nt], a[mt], bf);
        }
    }

    // ---------------- epilogue 2: +b2, store ----------------
    #pragma unroll
    for (int mt = 0; mt < 2; mt++) {
        #pragma unroll
        for (int h = 0; h < 2; h++) {
            const int r = mb + mt * 16 + grp + h * 8;
            const int q = q0 + (r >> 6);
            const int k = k0 + (r & 63);
            const size_t base = ((size_t)(b * NQ_ + q) * NK_ + k) * 64;
            #pragma unroll
            for (int nt = 0; nt < 4; nt++) {
                const int f = nb2 + nt * 8 + tig * 2;
                float2 v;
                v.x = c2[mt][nt][h * 2 + 0] + sB2[f];
                v.y = c2[mt][nt][h * 2 + 1] + sB2[f + 1];
                *(float2*)&out[base + f] = v;
            }
        }
    }
}

// =====================================================================
extern "C" void kernel_launch(void* const* d_in, const int* in_sizes, int n_in,
                              void* d_out, int out_size)
{
    (void)in_sizes; (void)n_in; (void)out_size;
    const float* q_equi = (const float*)d_in[0];
    const float* q_inv  = (const float*)d_in[1];
    const float* k_equi = (const float*)d_in[2];
    const float* k_inv  = (const float*)d_in[3];
    const float* Wqi = (const float*)d_in[4];  const float* bqi = (const float*)d_in[5];
    const float* Wki = (const float*)d_in[6];  const float* bki = (const float*)d_in[7];
    const float* Wqe = (const float*)d_in[8];  const float* bqe = (const float*)d_in[9];
    const float* Wke = (const float*)d_in[10]; const float* bke = (const float*)d_in[11];
    const float* W1  = (const float*)d_in[12]; const float* b1  = (const float*)d_in[13];
    const float* W2  = (const float*)d_in[14]; const float* b2  = (const float*)d_in[15];
    float* out = (float*)d_out;

    cudaFuncSetAttribute(pair_kernel, cudaFuncAttributeMaxDynamicSharedMemorySize, SMEM_BYTES);

    proj_kernel<<<dim3(B_ * NQ_, 2), 128>>>(q_equi, q_inv, k_equi, k_inv,
                                            Wqi, bqi, Wki, bki,
                                            Wqe, bqe, Wke, bke, W1, b1);
    pair_kernel<<<dim3(NK_ / 64, NQ_ / 2, B_), 256, SMEM_BYTES>>>(W1, W2, b2, out);
}

// round 4
// speedup vs baseline: 1.6242x; 1.6242x over previous
#include <cuda_runtime.h>
#include <cuda_fp16.h>
#include <stdint.h>
#include <stddef.h>

// ---------------- problem constants ----------------
#define B_    2
#define NQ_   768
#define NK_   768

// ---------------- static scratch ----------------
__device__ float    g_qe [B_*NQ_*96];       // [b,q, c*32+m]
__device__ float    g_ke [B_*NK_*96];
__device__ float    g_Aq [B_*NQ_*128];      // b1 + qi @ W1[0:32]
__device__ float    g_BkT[B_*128*NK_];      // [b][f][k]  (ki @ W1[32:64], transposed)
__device__ uint32_t g_W1h[128*36];          // [n][kq]  half2{W1[64+2kq][n], W1[64+2kq+1][n]}, kq<32 real
__device__ uint32_t g_W2h[64*68];           // [n][kq]  half2{W2[2kq][n],   W2[2kq+1][n]},   kq<64 real

// ---------------- helpers ----------------
__device__ __forceinline__ uint32_t smem_u32(const void* p){
    uint32_t a;
    asm("{ .reg .u64 t; cvta.to.shared.u64 t, %1; cvt.u32.u64 %0, t; }" : "=r"(a) : "l"(p));
    return a;
}
__device__ __forceinline__ float tanh_ap(float x){
    float y; asm("tanh.approx.f32 %0, %1;" : "=f"(y) : "f"(x)); return y;
}
__device__ __forceinline__ void ldmx4(uint32_t* r, uint32_t addr){
    asm volatile("ldmatrix.sync.aligned.m8n8.x4.shared.b16 {%0,%1,%2,%3}, [%4];"
        : "=r"(r[0]), "=r"(r[1]), "=r"(r[2]), "=r"(r[3]) : "r"(addr));
}
__device__ __forceinline__ void mma16816(float* d, const uint32_t* a, uint32_t b0, uint32_t b1){
    asm volatile(
        "mma.sync.aligned.m16n8k16.row.col.f32.f16.f16.f32 "
        "{%0,%1,%2,%3}, {%4,%5,%6,%7}, {%8,%9}, {%0,%1,%2,%3};"
        : "+f"(d[0]), "+f"(d[1]), "+f"(d[2]), "+f"(d[3])
        : "r"(a[0]), "r"(a[1]), "r"(a[2]), "r"(a[3]), "r"(b0), "r"(b1));
}

// ---------------- smem layout (bytes) ----------------
// fp16 tiles use row strides with (stride mod 128B)==16 -> conflict-free ldmatrix.
#define O_W1H 0                 // [128 n][72 k] fp16, stride 144B        = 18432
#define O_W2H 18432             // [ 64 n][136 k] fp16, stride 272B       = 17408
#define O_F   35840             // [128 p][72 k] fp16, stride 144B        = 18432
#define O_H   54272             // [128 p][136 k] fp16, stride 272B       = 34816
#define O_KE  89088             // [64][104] fp32                         = 26624
#define O_BK  115712            // [128 f][68 kk] fp32                    = 34816
#define O_AQ  150528            // [2][128] fp32                          = 1024
#define O_QE  151552            // [2][96] fp32                           = 768
#define O_B2  152320            // [64] fp32                              = 256
#define SMEM_TOTAL 152576

// =====================================================================
// Kernel W: pre-convert W1cd / W2 to packed fp16 B-tiles (run once)
// =====================================================================
__global__ __launch_bounds__(256)
void prep_kernel(const float* __restrict__ W1, const float* __restrict__ W2)
{
    const int idx = blockIdx.x * 256 + threadIdx.x;
    if (idx < 128*36) {
        const int n = idx / 36, kq = idx % 36;
        float a = 0.f, b = 0.f;
        if (kq < 32) {
            a = W1[(size_t)(64 + 2*kq    ) * 128 + n];
            b = W1[(size_t)(64 + 2*kq + 1) * 128 + n];
        }
        __half2 h = __floats2half2_rn(a, b);
        g_W1h[n*36 + kq] = *(const uint32_t*)&h;
    } else if (idx < 128*36 + 64*68) {
        const int j = idx - 128*36;
        const int n = j / 68, kq = j % 68;
        float a = 0.f, b = 0.f;
        if (kq < 64) {
            a = W2[(size_t)(2*kq    ) * 64 + n];
            b = W2[(size_t)(2*kq + 1) * 64 + n];
        }
        __half2 h = __floats2half2_rn(a, b);
        g_W2h[n*68 + kq] = *(const uint32_t*)&h;
    }
}

// =====================================================================
// Kernel P: per-row projections
// =====================================================================
__global__ __launch_bounds__(128)
void proj_kernel(const float* __restrict__ q_equi, const float* __restrict__ q_inv,
                 const float* __restrict__ k_equi, const float* __restrict__ k_inv,
                 const float* __restrict__ Wqi, const float* __restrict__ bqi,
                 const float* __restrict__ Wki, const float* __restrict__ bki,
                 const float* __restrict__ Wqe, const float* __restrict__ bqe,
                 const float* __restrict__ Wke, const float* __restrict__ bke,
                 const float* __restrict__ W1,  const float* __restrict__ b1)
{
    const int side = blockIdx.y;
    const int r    = blockIdx.x;           // b*768 + n
    const int tid  = threadIdx.x;

    const float* xe = side ? k_equi : q_equi;
    const float* xi = side ? k_inv  : q_inv;
    const float* We = side ? Wke : Wqe;
    const float* be = side ? bke : bqe;
    const float* Wi = side ? Wki : Wqi;
    const float* bi = side ? bki : bqi;
    float* oute = side ? g_ke : g_qe;

    __shared__ float sxe[768];
    __shared__ float sxi[256];
    __shared__ float spi[32];

    for (int i = tid; i < 768; i += 128) sxe[i] = xe[(size_t)r * 768 + i];
    for (int i = tid; i < 256; i += 128) sxi[i] = xi[(size_t)r * 256 + i];
    __syncthreads();

    if (tid < 96) {
        const int c = tid >> 5, m = tid & 31;
        float acc = be[m];
        #pragma unroll 4
        for (int d = 0; d < 256; d++)
            acc = fmaf(sxe[c * 256 + d], We[d * 32 + m], acc);
        oute[(size_t)r * 96 + c * 32 + m] = acc;
    } else {
        const int m = tid - 96;
        float acc = bi[m];
        #pragma unroll 4
        for (int d = 0; d < 256; d++)
            acc = fmaf(sxi[d], Wi[d * 32 + m], acc);
        spi[m] = acc;
    }
    __syncthreads();

    {
        float acc = side ? 0.0f : b1[tid];
        const int ro = side ? 32 : 0;
        #pragma unroll
        for (int m = 0; m < 32; m++)
            acc = fmaf(spi[m], W1[(ro + m) * 128 + tid], acc);
        if (side) {
            const int bb = r / 768, n = r - bb * 768;
            g_BkT[((size_t)bb * 128 + tid) * 768 + n] = acc;   // transposed store
        } else {
            g_Aq[(size_t)r * 128 + tid] = acc;
        }
    }
}

// =====================================================================
// Kernel B: pairwise tile kernel (fp16 mma + ldmatrix)
//   CTA = 2 q-rows x 64 k-rows = 128 pairs, 256 threads (8 warps).
// =====================================================================
__global__ __launch_bounds__(256, 1)
void pair_kernel(const float* __restrict__ b2g, float* __restrict__ out)
{
    extern __shared__ char sm[];
    __half* sW1h = (__half*)(sm + O_W1H);
    __half* sW2h = (__half*)(sm + O_W2H);
    __half* sF   = (__half*)(sm + O_F);
    __half* sH   = (__half*)(sm + O_H);
    float*  sKE  = (float*)(sm + O_KE);
    float*  sBK  = (float*)(sm + O_BK);
    float*  sAQ  = (float*)(sm + O_AQ);
    float*  sQE  = (float*)(sm + O_QE);
    float*  sB2  = (float*)(sm + O_B2);

    const int tid = threadIdx.x;
    const int b   = blockIdx.z;
    const int k0  = blockIdx.x * 64;
    const int q0  = blockIdx.y * 2;

    // ---------------- phase 1: loads ----------------
    {   // W1h: 1152 float4 ; W2h: 1088 float4 (pre-packed fp16)
        float4* d1 = (float4*)sW1h; const float4* s1 = (const float4*)g_W1h;
        for (int i = tid; i < 1152; i += 256) d1[i] = s1[i];
        float4* d2 = (float4*)sW2h; const float4* s2 = (const float4*)g_W2h;
        for (int i = tid; i < 1088; i += 256) d2[i] = s2[i];
    }
    {   // ke: 64 rows x 24 float4, padded stride 104 floats
        const float4* src = (const float4*)(g_ke + (size_t)(b * NK_ + k0) * 96);
        for (int i = tid; i < 1536; i += 256) {
            const int kk = i / 24, c = i % 24;
            *(float4*)(sKE + kk * 104 + c * 4) = src[kk * 24 + c];
        }
    }
    {   // BkT tile: 128 f-rows x 16 float4 (64 kk), stride 68 floats
        for (int i = tid; i < 2048; i += 256) {
            const int f = i >> 4, c = i & 15;
            *(float4*)(sBK + f * 68 + c * 4) =
                *(const float4*)(g_BkT + ((size_t)b * 128 + f) * 768 + k0 + c * 4);
        }
    }
    if (tid < 48)
        ((float4*)sQE)[tid] = *(const float4*)(g_qe + (size_t)(b * NQ_ + q0) * 96 + tid * 4);
    else if (tid < 112)
        ((float4*)sAQ)[tid - 48] = *(const float4*)(g_Aq + (size_t)(b * NQ_ + q0) * 128 + (tid - 48) * 4);
    else if (tid >= 128 && tid < 192)
        sB2[tid - 128] = b2g[tid - 128];
    __syncthreads();

    // ---------------- phase 2: feats (dot + dist) -> sF (fp16) ----------------
    #pragma unroll
    for (int it = 0; it < 4; it++) {
        const int g  = tid + it * 256;     // 1024 groups of 4 m-channels
        const int p  = g >> 3;             // pair 0..127
        const int m  = (g & 7) * 4;
        const int qq = p >> 6, kk = p & 63;
        float4 dot = make_float4(0.f, 0.f, 0.f, 0.f);
        float4 d2  = make_float4(0.f, 0.f, 0.f, 0.f);
        #pragma unroll
        for (int c = 0; c < 3; c++) {
            const float4 a  = *(const float4*)&sQE[qq * 96 + c * 32 + m];
            const float4 bb = *(const float4*)&sKE[kk * 104 + c * 32 + m];
            dot.x = fmaf(a.x, bb.x, dot.x);
            dot.y = fmaf(a.y, bb.y, dot.y);
            dot.z = fmaf(a.z, bb.z, dot.z);
            dot.w = fmaf(a.w, bb.w, dot.w);
            float dx = a.x - bb.x; d2.x = fmaf(dx, dx, d2.x);
            float dy = a.y - bb.y; d2.y = fmaf(dy, dy, d2.y);
            float dz = a.z - bb.z; d2.z = fmaf(dz, dz, d2.z);
            float dw = a.w - bb.w; d2.w = fmaf(dw, dw, d2.w);
        }
        __half2 h0 = __floats2half2_rn(dot.x, dot.y);
        __half2 h1 = __floats2half2_rn(dot.z, dot.w);
        __half2 h2 = __floats2half2_rn(sqrtf(d2.x), sqrtf(d2.y));
        __half2 h3 = __floats2half2_rn(sqrtf(d2.z), sqrtf(d2.w));
        *(__half2*)(sF + p * 72 + m)          = h0;
        *(__half2*)(sF + p * 72 + m + 2)      = h1;
        *(__half2*)(sF + p * 72 + 32 + m)     = h2;
        *(__half2*)(sF + p * 72 + 32 + m + 2) = h3;
    }
    __syncthreads();

    // ---------------- warp/lane geometry ----------------
    const int wid = tid >> 5, lane = tid & 31;
    const int grp = lane >> 2, tig = lane & 3;
    const int wm = wid & 3, wn = wid >> 2;     // warps 4(M) x 2(N)
    const int mb = wm * 32, nb = wn * 64;      // GEMM1 warp tile 32 x 64

    const uint32_t sFb  = smem_u32(sF);
    const uint32_t sHb  = smem_u32(sH);
    const uint32_t sW1b = smem_u32(sW1h);
    const uint32_t sW2b = smem_u32(sW2h);

    // ldmatrix lane address components
    const int arow = lane & 15;                // A: row within 16-row tile
    const int akof = (lane >> 4) * 16;         // A: +8 k (16 bytes)
    const int brow = (lane & 7) + ((lane >> 4) << 3);   // B: row within 16-n group
    const int bkof = ((lane >> 3) & 1) * 16;   // B: +8 k (16 bytes)

    // ---------------- phase 3: GEMM1  D1[128x128] = F[128x64] @ W1cd ----------------
    float c1[2][8][4];
    #pragma unroll
    for (int mt = 0; mt < 2; mt++)
        #pragma unroll
        for (int nt = 0; nt < 8; nt++)
            #pragma unroll
            for (int j = 0; j < 4; j++) c1[mt][nt][j] = 0.f;

    #pragma unroll
    for (int ks = 0; ks < 4; ks++) {
        const int kc = ks * 16;
        uint32_t a[2][4];
        #pragma unroll
        for (int mt = 0; mt < 2; mt++)
            ldmx4(a[mt], sFb + (mb + mt * 16 + arow) * 144 + kc * 2 + akof);
        #pragma unroll
        for (int np = 0; np < 4; np++) {
            uint32_t bb[4];
            ldmx4(bb, sW1b + (nb + np * 16 + brow) * 144 + kc * 2 + bkof);
            #pragma unroll
            for (int mt = 0; mt < 2; mt++) {
                mma16816(c1[mt][np * 2 + 0], a[mt], bb[0], bb[1]);
                mma16816(c1[mt][np * 2 + 1], a[mt], bb[2], bb[3]);
            }
        }
    }

    // ---------------- epilogue 1: +Aq +Bk (fp32), silu -> sH (fp16) ----------------
    {
        const int qq = mb >> 6;   // constant per warp
        #pragma unroll
        for (int nt = 0; nt < 8; nt++) {
            const int f0 = nb + nt * 8 + tig * 2;
            const float aq0 = sAQ[qq * 128 + f0];
            const float aq1 = sAQ[qq * 128 + f0 + 1];
            #pragma unroll
            for (int mt = 0; mt < 2; mt++) {
                #pragma unroll
                for (int h = 0; h < 2; h++) {
                    const int r  = mb + mt * 16 + grp + h * 8;
                    const int kk = r & 63;
                    const float v0 = c1[mt][nt][h * 2 + 0] + aq0 + sBK[f0 * 68 + kk];
                    const float v1 = c1[mt][nt][h * 2 + 1] + aq1 + sBK[(f0 + 1) * 68 + kk];
                    const float hv0 = 0.5f * v0, hv1 = 0.5f * v1;
                    const float s0 = fmaf(hv0, tanh_ap(hv0), hv0);  // v*sigmoid(v)
                    const float s1 = fmaf(hv1, tanh_ap(hv1), hv1);
                    *(__half2*)(sH + r * 136 + f0) = __floats2half2_rn(s0, s1);
                }
            }
        }
    }
    __syncthreads();

    // ---------------- phase 4: GEMM2  D2[128x64] = H[128x128] @ W2 ----------------
    const int nb2 = wn * 32;                   // warp tile 32 x 32
    float c2[2][4][4];
    #pragma unroll
    for (int mt = 0; mt < 2; mt++)
        #pragma unroll
        for (int nt = 0; nt < 4; nt++)
            #pragma unroll
            for (int j = 0; j < 4; j++) c2[mt][nt][j] = 0.f;

    #pragma unroll
    for (int ks = 0; ks < 8; ks++) {
        const int kc = ks * 16;
        uint32_t a[2][4];
        #pragma unroll
        for (int mt = 0; mt < 2; mt++)
            ldmx4(a[mt], sHb + (mb + mt * 16 + arow) * 272 + kc * 2 + akof);
        #pragma unroll
        for (int np = 0; np < 2; np++) {
            uint32_t bb[4];
            ldmx4(bb, sW2b + (nb2 + np * 16 + brow) * 272 + kc * 2 + bkof);
            #pragma unroll
            for (int mt = 0; mt < 2; mt++) {
                mma16816(c2[mt][np * 2 + 0], a[mt], bb[0], bb[1]);
                mma16816(c2[mt][np * 2 + 1], a[mt], bb[2], bb[3]);
            }
        }
    }

    // ---------------- epilogue 2: +b2, store ----------------
    #pragma unroll
    for (int mt = 0; mt < 2; mt++) {
        #pragma unroll
        for (int h = 0; h < 2; h++) {
            const int r = mb + mt * 16 + grp + h * 8;
            const int q = q0 + (r >> 6);
            const int k = k0 + (r & 63);
            const size_t base = ((size_t)(b * NQ_ + q) * NK_ + k) * 64;
            #pragma unroll
            for (int nt = 0; nt < 4; nt++) {
                const int f = nb2 + nt * 8 + tig * 2;
                float2 v;
                v.x = c2[mt][nt][h * 2 + 0] + sB2[f];
                v.y = c2[mt][nt][h * 2 + 1] + sB2[f + 1];
                *(float2*)&out[base + f] = v;
            }
        }
    }
}

// =====================================================================
extern "C" void kernel_launch(void* const* d_in, const int* in_sizes, int n_in,
                              void* d_out, int out_size)
{
    (void)in_sizes; (void)n_in; (void)out_size;
    const float* q_equi = (const float*)d_in[0];
    const float* q_inv  = (const float*)d_in[1];
    const float* k_equi = (const float*)d_in[2];
    const float* k_inv  = (const float*)d_in[3];
    const float* Wqi = (const float*)d_in[4];  const float* bqi = (const float*)d_in[5];
    const float* Wki = (const float*)d_in[6];  const float* bki = (const float*)d_in[7];
    const float* Wqe = (const float*)d_in[8];  const float* bqe = (const float*)d_in[9];
    const float* Wke = (const float*)d_in[10]; const float* bke = (const float*)d_in[11];
    const float* W1  = (const float*)d_in[12]; const float* b1  = (const float*)d_in[13];
    const float* W2  = (const float*)d_in[14]; const float* b2  = (const float*)d_in[15];
    float* out = (float*)d_out;

    cudaFuncSetAttribute(pair_kernel, cudaFuncAttributeMaxDynamicSharedMemorySize, SMEM_TOTAL);

    prep_kernel<<<35, 256>>>(W1, W2);
    proj_kernel<<<dim3(B_ * NQ_, 2), 128>>>(q_equi, q_inv, k_equi, k_inv,
                                            Wqi, bqi, Wki, bki,
                                            Wqe, bqe, Wke, bke, W1, b1);
    pair_kernel<<<dim3(NK_ / 64, NQ_ / 2, B_), 256, SMEM_TOTAL>>>(b2, out);
}

// round 5
// speedup vs baseline: 2.8262x; 1.7400x over previous
#include <cuda_runtime.h>
#include <cuda_fp16.h>
#include <stdint.h>
#include <stddef.h>

// ---------------- problem constants ----------------
#define B_    2
#define NQ_   768
#define NK_   768

// ---------------- static scratch ----------------
__device__ float    g_qe [B_*NQ_*96];       // [b,q, c*32+m]
__device__ float    g_ke [B_*NK_*96];
__device__ float    g_Aq [B_*NQ_*128];      // b1 + qi @ W1[0:32]
__device__ float    g_BkT[B_*128*NK_];      // [b][f][k]  (ki @ W1[32:64], transposed)
__device__ uint32_t g_W1h[128*36];          // [n][kq] half2{W1[64+2kq][n], W1[64+2kq+1][n]}
__device__ uint32_t g_W2h[64*68];           // [n][kq] half2{W2[2kq][n],   W2[2kq+1][n]}

// ---------------- helpers ----------------
__device__ __forceinline__ uint32_t smem_u32(const void* p){
    uint32_t a;
    asm("{ .reg .u64 t; cvta.to.shared.u64 t, %1; cvt.u32.u64 %0, t; }" : "=r"(a) : "l"(p));
    return a;
}
__device__ __forceinline__ float tanh_ap(float x){
    float y; asm("tanh.approx.f32 %0, %1;" : "=f"(y) : "f"(x)); return y;
}
__device__ __forceinline__ float silu_f(float v){
    const float hv = 0.5f * v;
    return fmaf(hv, tanh_ap(hv), hv);          // v * sigmoid(v)
}
__device__ __forceinline__ uint32_t pack2(float a, float b){
    __half2 h = __floats2half2_rn(a, b);
    return *(const uint32_t*)&h;
}
__device__ __forceinline__ void ldmx4(uint32_t* r, uint32_t addr){
    asm volatile("ldmatrix.sync.aligned.m8n8.x4.shared.b16 {%0,%1,%2,%3}, [%4];"
        : "=r"(r[0]), "=r"(r[1]), "=r"(r[2]), "=r"(r[3]) : "r"(addr));
}
__device__ __forceinline__ void mma16816(float* d, const uint32_t* a, uint32_t b0, uint32_t b1){
    asm volatile(
        "mma.sync.aligned.m16n8k16.row.col.f32.f16.f16.f32 "
        "{%0,%1,%2,%3}, {%4,%5,%6,%7}, {%8,%9}, {%0,%1,%2,%3};"
        : "+f"(d[0]), "+f"(d[1]), "+f"(d[2]), "+f"(d[3])
        : "r"(a[0]), "r"(a[1]), "r"(a[2]), "r"(a[3]), "r"(b0), "r"(b1));
}

// ---------------- smem layout (bytes) ----------------
// fp16 tiles: row stride mod 128B == 16 -> conflict-free ldmatrix.
#define O_W1H 0                 // [128 n][72 k] fp16, stride 144B   = 18432
#define O_W2H 18432             // [ 64 n][136 k] fp16, stride 272B  = 17408
#define O_F   35840             // [128 p][72 k] fp16, stride 144B   = 18432
#define O_KE  54272             // [64][96] fp32 packed              = 24576
#define O_BK  78848             // [128 f][68 kk] fp32               = 34816
#define O_AQ  113664            // [2][128] fp32                     = 1024
#define O_QE  114688            // [2][96] fp32                      = 768
#define O_B2  115456            // [64] fp32                         = 256
#define SMEM_TOTAL 115712

// =====================================================================
// Kernel W: pre-convert W1cd / W2 to packed fp16 B-tiles (run once)
// =====================================================================
__global__ __launch_bounds__(256)
void prep_kernel(const float* __restrict__ W1, const float* __restrict__ W2)
{
    const int idx = blockIdx.x * 256 + threadIdx.x;
    if (idx < 128*36) {
        const int n = idx / 36, kq = idx % 36;
        float a = 0.f, b = 0.f;
        if (kq < 32) {
            a = W1[(size_t)(64 + 2*kq    ) * 128 + n];
            b = W1[(size_t)(64 + 2*kq + 1) * 128 + n];
        }
        g_W1h[n*36 + kq] = pack2(a, b);
    } else if (idx < 128*36 + 64*68) {
        const int j = idx - 128*36;
        const int n = j / 68, kq = j % 68;
        float a = 0.f, b = 0.f;
        if (kq < 64) {
            a = W2[(size_t)(2*kq    ) * 64 + n];
            b = W2[(size_t)(2*kq + 1) * 64 + n];
        }
        g_W2h[n*68 + kq] = pack2(a, b);
    }
}

// =====================================================================
// Kernel P: per-row projections
// =====================================================================
__global__ __launch_bounds__(128)
void proj_kernel(const float* __restrict__ q_equi, const float* __restrict__ q_inv,
                 const float* __restrict__ k_equi, const float* __restrict__ k_inv,
                 const float* __restrict__ Wqi, const float* __restrict__ bqi,
                 const float* __restrict__ Wki, const float* __restrict__ bki,
                 const float* __restrict__ Wqe, const float* __restrict__ bqe,
                 const float* __restrict__ Wke, const float* __restrict__ bke,
                 const float* __restrict__ W1,  const float* __restrict__ b1)
{
    const int side = blockIdx.y;
    const int r    = blockIdx.x;           // b*768 + n
    const int tid  = threadIdx.x;

    const float* xe = side ? k_equi : q_equi;
    const float* xi = side ? k_inv  : q_inv;
    const float* We = side ? Wke : Wqe;
    const float* be = side ? bke : bqe;
    const float* Wi = side ? Wki : Wqi;
    const float* bi = side ? bki : bqi;
    float* oute = side ? g_ke : g_qe;

    __shared__ float sxe[768];
    __shared__ float sxi[256];
    __shared__ float spi[32];

    for (int i = tid; i < 768; i += 128) sxe[i] = xe[(size_t)r * 768 + i];
    for (int i = tid; i < 256; i += 128) sxi[i] = xi[(size_t)r * 256 + i];
    __syncthreads();

    if (tid < 96) {
        const int c = tid >> 5, m = tid & 31;
        float acc = be[m];
        #pragma unroll 4
        for (int d = 0; d < 256; d++)
            acc = fmaf(sxe[c * 256 + d], We[d * 32 + m], acc);
        oute[(size_t)r * 96 + c * 32 + m] = acc;
    } else {
        const int m = tid - 96;
        float acc = bi[m];
        #pragma unroll 4
        for (int d = 0; d < 256; d++)
            acc = fmaf(sxi[d], Wi[d * 32 + m], acc);
        spi[m] = acc;
    }
    __syncthreads();

    {
        float acc = side ? 0.0f : b1[tid];
        const int ro = side ? 32 : 0;
        #pragma unroll
        for (int m = 0; m < 32; m++)
            acc = fmaf(spi[m], W1[(ro + m) * 128 + tid], acc);
        if (side) {
            const int bb = r / 768, n = r - bb * 768;
            g_BkT[((size_t)bb * 128 + tid) * 768 + n] = acc;   // transposed store
        } else {
            g_Aq[(size_t)r * 128 + tid] = acc;
        }
    }
}

// =====================================================================
// Kernel B: pairwise tile kernel (fp16 mma + ldmatrix, register-resident H)
//   CTA = 2 q-rows x 64 k-rows = 128 pairs, 256 threads (8 warps).
//   Warp tile: GEMM1 16(M) x 128(N), GEMM2 16(M) x 64(N).
//   GEMM1 accumulators are converted IN REGISTERS to GEMM2 A-fragments.
// =====================================================================
__global__ __launch_bounds__(256, 2)
void pair_kernel(const float* __restrict__ b2g, float* __restrict__ out)
{
    extern __shared__ char sm[];
    __half* sW1h = (__half*)(sm + O_W1H);
    __half* sW2h = (__half*)(sm + O_W2H);
    __half* sF   = (__half*)(sm + O_F);
    float*  sKE  = (float*)(sm + O_KE);
    float*  sBK  = (float*)(sm + O_BK);
    float*  sAQ  = (float*)(sm + O_AQ);
    float*  sQE  = (float*)(sm + O_QE);
    float*  sB2  = (float*)(sm + O_B2);

    const int tid = threadIdx.x;
    const int b   = blockIdx.z;
    const int k0  = blockIdx.x * 64;
    const int q0  = blockIdx.y * 2;

    // ---------------- phase 1: loads ----------------
    {   // pre-packed fp16 weights
        float4* d1 = (float4*)sW1h; const float4* s1 = (const float4*)g_W1h;
        for (int i = tid; i < 1152; i += 256) d1[i] = s1[i];
        float4* d2 = (float4*)sW2h; const float4* s2 = (const float4*)g_W2h;
        for (int i = tid; i < 1088; i += 256) d2[i] = s2[i];
    }
    {   // ke: packed 96-float rows, straight copy
        const float4* src = (const float4*)(g_ke + (size_t)(b * NK_ + k0) * 96);
        float4* dst = (float4*)sKE;
        for (int i = tid; i < 1536; i += 256) dst[i] = src[i];
    }
    {   // BkT tile: 128 f-rows x 16 float4 (64 kk), stride 68 floats
        for (int i = tid; i < 2048; i += 256) {
            const int f = i >> 4, c = i & 15;
            *(float4*)(sBK + f * 68 + c * 4) =
                *(const float4*)(g_BkT + ((size_t)b * 128 + f) * 768 + k0 + c * 4);
        }
    }
    if (tid < 48)
        ((float4*)sQE)[tid] = *(const float4*)(g_qe + (size_t)(b * NQ_ + q0) * 96 + tid * 4);
    else if (tid < 112)
        ((float4*)sAQ)[tid - 48] = *(const float4*)(g_Aq + (size_t)(b * NQ_ + q0) * 128 + (tid - 48) * 4);
    else if (tid >= 128 && tid < 192)
        sB2[tid - 128] = b2g[tid - 128];
    __syncthreads();

    // ---------------- phase 2: feats (dot + dist) -> sF (fp16) ----------------
    #pragma unroll
    for (int it = 0; it < 4; it++) {
        const int g  = tid + it * 256;     // 1024 groups of 4 m-channels
        const int p  = g >> 3;             // pair 0..127
        const int m  = (g & 7) * 4;
        const int qq = p >> 6, kk = p & 63;
        float4 dot = make_float4(0.f, 0.f, 0.f, 0.f);
        float4 d2  = make_float4(0.f, 0.f, 0.f, 0.f);
        #pragma unroll
        for (int c = 0; c < 3; c++) {
            const float4 a  = *(const float4*)&sQE[qq * 96 + c * 32 + m];
            const float4 bb = *(const float4*)&sKE[kk * 96 + c * 32 + m];
            dot.x = fmaf(a.x, bb.x, dot.x);
            dot.y = fmaf(a.y, bb.y, dot.y);
            dot.z = fmaf(a.z, bb.z, dot.z);
            dot.w = fmaf(a.w, bb.w, dot.w);
            float dx = a.x - bb.x; d2.x = fmaf(dx, dx, d2.x);
            float dy = a.y - bb.y; d2.y = fmaf(dy, dy, d2.y);
            float dz = a.z - bb.z; d2.z = fmaf(dz, dz, d2.z);
            float dw = a.w - bb.w; d2.w = fmaf(dw, dw, d2.w);
        }
        *(__half2*)(sF + p * 72 + m)          = __floats2half2_rn(dot.x, dot.y);
        *(__half2*)(sF + p * 72 + m + 2)      = __floats2half2_rn(dot.z, dot.w);
        *(__half2*)(sF + p * 72 + 32 + m)     = __floats2half2_rn(sqrtf(d2.x), sqrtf(d2.y));
        *(__half2*)(sF + p * 72 + 32 + m + 2) = __floats2half2_rn(sqrtf(d2.z), sqrtf(d2.w));
    }
    __syncthreads();

    // ---------------- warp/lane geometry ----------------
    const int wid = tid >> 5, lane = tid & 31;
    const int grp = lane >> 2, tig = lane & 3;
    const int mb  = wid * 16;                  // warp M-tile: rows mb..mb+15

    const uint32_t sFb  = smem_u32(sF);
    const uint32_t sW1b = smem_u32(sW1h);
    const uint32_t sW2b = smem_u32(sW2h);

    // ldmatrix lane address components
    const int arow = lane & 15;                         // A: row in 16-row tile
    const int akof = (lane >> 4) * 16;                  // A: +8 k (16 B)
    const int brow = (lane & 7) + ((lane >> 4) << 3);   // B: row in 16-n group
    const int bkof = ((lane >> 3) & 1) * 16;            // B: +8 k (16 B)

    // ---------------- GEMM1: D1[16x128] = F[16x64] @ W1cd ----------------
    float c1[16][4];
    #pragma unroll
    for (int nt = 0; nt < 16; nt++)
        #pragma unroll
        for (int j = 0; j < 4; j++) c1[nt][j] = 0.f;

    #pragma unroll
    for (int ks = 0; ks < 4; ks++) {
        uint32_t a[4];
        ldmx4(a, sFb + (mb + arow) * 144 + ks * 32 + akof);
        #pragma unroll
        for (int np = 0; np < 8; np++) {
            uint32_t bb[4];
            ldmx4(bb, sW1b + (np * 16 + brow) * 144 + ks * 32 + bkof);
            mma16816(c1[np * 2 + 0], a, bb[0], bb[1]);
            mma16816(c1[np * 2 + 1], a, bb[2], bb[3]);
        }
    }

    // ---------------- epilogue 1 (in registers): +Aq +Bk, silu -> GEMM2 A-frags ----
    uint32_t a2[8][4];
    {
        const int qq  = wid >> 2;                       // q row of this warp's M-tile
        const int kkb = (wid & 3) * 16 + grp;           // k row (c[0,1]); +8 for c[2,3]
        #pragma unroll
        for (int kt = 0; kt < 8; kt++) {
            #pragma unroll
            for (int hnt = 0; hnt < 2; hnt++) {
                const int nt = kt * 2 + hnt;
                const int f  = nt * 8 + tig * 2;
                const float aq0 = sAQ[qq * 128 + f];
                const float aq1 = sAQ[qq * 128 + f + 1];
                const float* bk0 = sBK + f * 68;
                const float* bk1 = sBK + (f + 1) * 68;
                const float v0 = silu_f(c1[nt][0] + aq0 + bk0[kkb]);
                const float v1 = silu_f(c1[nt][1] + aq1 + bk1[kkb]);
                const float v2 = silu_f(c1[nt][2] + aq0 + bk0[kkb + 8]);
                const float v3 = silu_f(c1[nt][3] + aq1 + bk1[kkb + 8]);
                a2[kt][hnt * 2 + 0] = pack2(v0, v1);    // row grp
                a2[kt][hnt * 2 + 1] = pack2(v2, v3);    // row grp+8
            }
        }
    }

    // ---------------- GEMM2: D2[16x64] = H[16x128] @ W2 (A from registers) -------
    float c2[8][4];
    #pragma unroll
    for (int nt = 0; nt < 8; nt++)
        #pragma unroll
        for (int j = 0; j < 4; j++) c2[nt][j] = 0.f;

    #pragma unroll
    for (int ks = 0; ks < 8; ks++) {
        #pragma unroll
        for (int np = 0; np < 4; np++) {
            uint32_t bb[4];
            ldmx4(bb, sW2b + (np * 16 + brow) * 272 + ks * 32 + bkof);
            mma16816(c2[np * 2 + 0], a2[ks], bb[0], bb[1]);
            mma16816(c2[np * 2 + 1], a2[ks], bb[2], bb[3]);
        }
    }

    // ---------------- epilogue 2: +b2, store ----------------
    {
        const int q = q0 + (wid >> 2);
        const int kbase = k0 + (wid & 3) * 16 + grp;
        #pragma unroll
        for (int h = 0; h < 2; h++) {
            const size_t base = ((size_t)(b * NQ_ + q) * NK_ + kbase + h * 8) * 64;
            #pragma unroll
            for (int nt = 0; nt < 8; nt++) {
                const int f = nt * 8 + tig * 2;
                float2 v;
                v.x = c2[nt][h * 2 + 0] + sB2[f];
                v.y = c2[nt][h * 2 + 1] + sB2[f + 1];
                *(float2*)&out[base + f] = v;
            }
        }
    }
}

// =====================================================================
extern "C" void kernel_launch(void* const* d_in, const int* in_sizes, int n_in,
                              void* d_out, int out_size)
{
    (void)in_sizes; (void)n_in; (void)out_size;
    const float* q_equi = (const float*)d_in[0];
    const float* q_inv  = (const float*)d_in[1];
    const float* k_equi = (const float*)d_in[2];
    const float* k_inv  = (const float*)d_in[3];
    const float* Wqi = (const float*)d_in[4];  const float* bqi = (const float*)d_in[5];
    const float* Wki = (const float*)d_in[6];  const float* bki = (const float*)d_in[7];
    const float* Wqe = (const float*)d_in[8];  const float* bqe = (const float*)d_in[9];
    const float* Wke = (const float*)d_in[10]; const float* bke = (const float*)d_in[11];
    const float* W1  = (const float*)d_in[12]; const float* b1  = (const float*)d_in[13];
    const float* W2  = (const float*)d_in[14]; const float* b2  = (const float*)d_in[15];
    float* out = (float*)d_out;

    cudaFuncSetAttribute(pair_kernel, cudaFuncAttributeMaxDynamicSharedMemorySize, SMEM_TOTAL);

    prep_kernel<<<35, 256>>>(W1, W2);
    proj_kernel<<<dim3(B_ * NQ_, 2), 128>>>(q_equi, q_inv, k_equi, k_inv,
                                            Wqi, bqi, Wki, bki,
                                            Wqe, bqe, Wke, bke, W1, b1);
    pair_kernel<<<dim3(NK_ / 64, NQ_ / 2, B_), 256, SMEM_TOTAL>>>(b2, out);
}

// round 6
// speedup vs baseline: 3.9779x; 1.4075x over previous
#include <cuda_runtime.h>
#include <cuda_fp16.h>
#include <stdint.h>
#include <stddef.h>

// ---------------- problem constants ----------------
#define B_    2
#define NQ_   768
#define NK_   768

// ---------------- static scratch ----------------
__device__ float    g_qe [B_*NQ_*96];       // [b,q, c*32+m]
__device__ float    g_ke [B_*NK_*96];
__device__ float    g_Aq [B_*NQ_*128];      // b1 + qi @ W1[0:32]
__device__ uint32_t g_kih[B_*NK_*16];       // [b,k][16] packed fp16 ki (32 vals)
__device__ uint32_t g_W1h[128*52];          // [n][kq] B-tile for A=[dot|dist|ki] (K=96)
__device__ uint32_t g_W2h[64*68];           // [n][kq] half2{W2[2kq][n], W2[2kq+1][n]}

// ---------------- helpers ----------------
__device__ __forceinline__ uint32_t smem_u32(const void* p){
    uint32_t a;
    asm("{ .reg .u64 t; cvta.to.shared.u64 t, %1; cvt.u32.u64 %0, t; }" : "=r"(a) : "l"(p));
    return a;
}
__device__ __forceinline__ float tanh_ap(float x){
    float y; asm("tanh.approx.f32 %0, %1;" : "=f"(y) : "f"(x)); return y;
}
__device__ __forceinline__ float silu_f(float v){
    const float hv = 0.5f * v;
    return fmaf(hv, tanh_ap(hv), hv);          // v * sigmoid(v)
}
__device__ __forceinline__ uint32_t pack2(float a, float b){
    __half2 h = __floats2half2_rn(a, b);
    return *(const uint32_t*)&h;
}
__device__ __forceinline__ void ldmx4(uint32_t* r, uint32_t addr){
    asm volatile("ldmatrix.sync.aligned.m8n8.x4.shared.b16 {%0,%1,%2,%3}, [%4];"
        : "=r"(r[0]), "=r"(r[1]), "=r"(r[2]), "=r"(r[3]) : "r"(addr));
}
__device__ __forceinline__ void mma16816(float* d, const uint32_t* a, uint32_t b0, uint32_t b1){
    asm volatile(
        "mma.sync.aligned.m16n8k16.row.col.f32.f16.f16.f32 "
        "{%0,%1,%2,%3}, {%4,%5,%6,%7}, {%8,%9}, {%0,%1,%2,%3};"
        : "+f"(d[0]), "+f"(d[1]), "+f"(d[2]), "+f"(d[3])
        : "r"(a[0]), "r"(a[1]), "r"(a[2]), "r"(a[3]), "r"(b0), "r"(b1));
}

// ---------------- smem layout (bytes) ----------------
// fp16 tiles: row stride = odd multiple of 16B -> conflict-free ldmatrix.
#define O_W1H 0                 // [128 n][104 k] fp16, stride 208B  = 26624
#define O_W2H 26624             // [ 64 n][136 k] fp16, stride 272B  = 17408
#define O_F   44032             // [128 p][104 k] fp16, stride 208B  = 26624
#define O_KE  70656             // [64][96] fp32 packed              = 24576
#define O_AQ  95232             // [8][128] fp32                     = 4096
#define O_QE  99328             // [8][96] fp32                      = 3072
#define O_B2  102400            // [64] fp32                         = 256
#define SMEM_TOTAL 102656

// =====================================================================
// Kernel W: pre-convert weights to packed fp16 B-tiles (run once)
//   W1h: A-order [dot(0:32) | dist(32:64) | ki(64:96)]
//        -> W1 row map: a<64 ? 64+a : a-32
// =====================================================================
__global__ __launch_bounds__(256)
void prep_kernel(const float* __restrict__ W1, const float* __restrict__ W2)
{
    const int idx = blockIdx.x * 256 + threadIdx.x;
    if (idx < 128*52) {
        const int n = idx / 52, kq = idx % 52;
        float a = 0.f, b = 0.f;
        if (kq < 48) {
            const int a0 = 2*kq, a1 = 2*kq + 1;
            const int r0 = (a0 < 64) ? (64 + a0) : (a0 - 32);
            const int r1 = (a1 < 64) ? (64 + a1) : (a1 - 32);
            a = W1[(size_t)r0 * 128 + n];
            b = W1[(size_t)r1 * 128 + n];
        }
        g_W1h[n*52 + kq] = pack2(a, b);
    } else if (idx < 128*52 + 64*68) {
        const int j = idx - 128*52;
        const int n = j / 68, kq = j % 68;
        float a = 0.f, b = 0.f;
        if (kq < 64) {
            a = W2[(size_t)(2*kq    ) * 64 + n];
            b = W2[(size_t)(2*kq + 1) * 64 + n];
        }
        g_W2h[n*68 + kq] = pack2(a, b);
    }
}

// =====================================================================
// Kernel P: per-row projections
// =====================================================================
__global__ __launch_bounds__(128)
void proj_kernel(const float* __restrict__ q_equi, const float* __restrict__ q_inv,
                 const float* __restrict__ k_equi, const float* __restrict__ k_inv,
                 const float* __restrict__ Wqi, const float* __restrict__ bqi,
                 const float* __restrict__ Wki, const float* __restrict__ bki,
                 const float* __restrict__ Wqe, const float* __restrict__ bqe,
                 const float* __restrict__ Wke, const float* __restrict__ bke,
                 const float* __restrict__ W1,  const float* __restrict__ b1)
{
    const int side = blockIdx.y;
    const int r    = blockIdx.x;           // b*768 + n
    const int tid  = threadIdx.x;

    const float* xe = side ? k_equi : q_equi;
    const float* xi = side ? k_inv  : q_inv;
    const float* We = side ? Wke : Wqe;
    const float* be = side ? bke : bqe;
    const float* Wi = side ? Wki : Wqi;
    const float* bi = side ? bki : bqi;
    float* oute = side ? g_ke : g_qe;

    __shared__ float sxe[768];
    __shared__ float sxi[256];
    __shared__ float spi[32];

    for (int i = tid; i < 768; i += 128) sxe[i] = xe[(size_t)r * 768 + i];
    for (int i = tid; i < 256; i += 128) sxi[i] = xi[(size_t)r * 256 + i];
    __syncthreads();

    if (tid < 96) {
        const int c = tid >> 5, m = tid & 31;
        float acc = be[m];
        #pragma unroll 4
        for (int d = 0; d < 256; d++)
            acc = fmaf(sxe[c * 256 + d], We[d * 32 + m], acc);
        oute[(size_t)r * 96 + c * 32 + m] = acc;
    } else {
        const int m = tid - 96;
        float acc = bi[m];
        #pragma unroll 4
        for (int d = 0; d < 256; d++)
            acc = fmaf(sxi[d], Wi[d * 32 + m], acc);
        spi[m] = acc;
    }
    __syncthreads();

    if (side) {
        // pack ki (32 vals) to fp16 pairs
        if (tid < 16)
            g_kih[(size_t)r * 16 + tid] = pack2(spi[2*tid], spi[2*tid + 1]);
    } else {
        float acc = b1[tid];
        #pragma unroll
        for (int m = 0; m < 32; m++)
            acc = fmaf(spi[m], W1[m * 128 + tid], acc);
        g_Aq[(size_t)r * 128 + tid] = acc;
    }
}

// =====================================================================
// Kernel B: pairwise kernel.
//   CTA = 8 q-rows x 64 k-rows; 4 passes of (2q x 64k, M=128).
//   GEMM1: A=[dot|dist|ki] (K=96) @ W1h ; epi: +Aq, silu (regs) ; GEMM2 (K=128)
// =====================================================================
__global__ __launch_bounds__(256, 2)
void pair_kernel(const float* __restrict__ b2g, float* __restrict__ out)
{
    extern __shared__ char sm[];
    __half*   sW1h = (__half*)(sm + O_W1H);
    __half*   sW2h = (__half*)(sm + O_W2H);
    __half*   sF   = (__half*)(sm + O_F);
    uint32_t* sFu  = (uint32_t*)(sm + O_F);
    float*    sKE  = (float*)(sm + O_KE);
    float*    sAQ  = (float*)(sm + O_AQ);
    float*    sQE  = (float*)(sm + O_QE);
    float*    sB2  = (float*)(sm + O_B2);

    const int tid = threadIdx.x;
    const int b   = blockIdx.z;
    const int k0  = blockIdx.x * 64;
    const int q0  = blockIdx.y * 8;

    // ---------------- phase 0: one-time loads ----------------
    {   // pre-packed fp16 weights: W1h 1664 f4, W2h 1088 f4
        float4* d1 = (float4*)sW1h; const float4* s1 = (const float4*)g_W1h;
        for (int i = tid; i < 1664; i += 256) d1[i] = s1[i];
        float4* d2 = (float4*)sW2h; const float4* s2 = (const float4*)g_W2h;
        for (int i = tid; i < 1088; i += 256) d2[i] = s2[i];
    }
    {   // ke: packed 96-float rows
        const float4* src = (const float4*)(g_ke + (size_t)(b * NK_ + k0) * 96);
        float4* dst = (float4*)sKE;
        for (int i = tid; i < 1536; i += 256) dst[i] = src[i];
    }
    {   // ki -> F cols 64..95 (uint32 cols 32..47), rows kk and 64+kk
        for (int i = tid; i < 1024; i += 256) {
            const int kk = i >> 4, c = i & 15;
            const uint32_t v = g_kih[(size_t)(b * NK_ + k0 + kk) * 16 + c];
            sFu[kk * 52 + 32 + c]        = v;
            sFu[(64 + kk) * 52 + 32 + c] = v;
        }
    }
    {   // qe: 8 rows x 24 f4 ; Aq: 8 rows x 32 f4
        if (tid < 192)
            ((float4*)sQE)[tid] = *(const float4*)(g_qe + (size_t)(b * NQ_ + q0) * 96 + tid * 4);
        for (int i = tid; i < 256; i += 256)
            ((float4*)sAQ)[i] = *(const float4*)(g_Aq + (size_t)(b * NQ_ + q0) * 128 + i * 4);
        if (tid >= 192 && tid < 256) sB2[tid - 192] = b2g[tid - 192];
    }
    __syncthreads();

    // ---------------- warp/lane geometry ----------------
    const int wid = tid >> 5, lane = tid & 31;
    const int grp = lane >> 2, tig = lane & 3;
    const int mb  = wid * 16;                  // warp M-tile rows

    const uint32_t sFb  = smem_u32(sF);
    const uint32_t sW1b = smem_u32(sW1h);
    const uint32_t sW2b = smem_u32(sW2h);

    const int arow = lane & 15;
    const int akof = (lane >> 4) * 16;
    const int brow = (lane & 7) + ((lane >> 4) << 3);
    const int bkof = ((lane >> 3) & 1) * 16;

    // ---------------- pass loop: 4 x (2q x 64k) ----------------
    for (int pass = 0; pass < 4; pass++) {
        // ---- feats: dot + dist -> F cols 0..63 (fp16) ----
        #pragma unroll
        for (int it = 0; it < 4; it++) {
            const int g  = tid + it * 256;
            const int p  = g >> 3;             // pair 0..127
            const int m  = (g & 7) * 4;
            const int qq = pass * 2 + (p >> 6), kk = p & 63;
            float4 dot = make_float4(0.f, 0.f, 0.f, 0.f);
            float4 d2  = make_float4(0.f, 0.f, 0.f, 0.f);
            #pragma unroll
            for (int c = 0; c < 3; c++) {
                const float4 a  = *(const float4*)&sQE[qq * 96 + c * 32 + m];
                const float4 bb = *(const float4*)&sKE[kk * 96 + c * 32 + m];
                dot.x = fmaf(a.x, bb.x, dot.x);
                dot.y = fmaf(a.y, bb.y, dot.y);
                dot.z = fmaf(a.z, bb.z, dot.z);
                dot.w = fmaf(a.w, bb.w, dot.w);
                float dx = a.x - bb.x; d2.x = fmaf(dx, dx, d2.x);
                float dy = a.y - bb.y; d2.y = fmaf(dy, dy, d2.y);
                float dz = a.z - bb.z; d2.z = fmaf(dz, dz, d2.z);
                float dw = a.w - bb.w; d2.w = fmaf(dw, dw, d2.w);
            }
            *(__half2*)(sF + p * 104 + m)          = __floats2half2_rn(dot.x, dot.y);
            *(__half2*)(sF + p * 104 + m + 2)      = __floats2half2_rn(dot.z, dot.w);
            *(__half2*)(sF + p * 104 + 32 + m)     = __floats2half2_rn(sqrtf(d2.x), sqrtf(d2.y));
            *(__half2*)(sF + p * 104 + 32 + m + 2) = __floats2half2_rn(sqrtf(d2.z), sqrtf(d2.w));
        }
        __syncthreads();

        // ---- GEMM1: D1[16x128] = F[16x96] @ W1h ----
        float c1[16][4];
        #pragma unroll
        for (int nt = 0; nt < 16; nt++)
            #pragma unroll
            for (int j = 0; j < 4; j++) c1[nt][j] = 0.f;

        #pragma unroll
        for (int ks = 0; ks < 6; ks++) {
            uint32_t a[4];
            ldmx4(a, sFb + (mb + arow) * 208 + ks * 32 + akof);
            #pragma unroll
            for (int np = 0; np < 8; np++) {
                uint32_t bb[4];
                ldmx4(bb, sW1b + (np * 16 + brow) * 208 + ks * 32 + bkof);
                mma16816(c1[np * 2 + 0], a, bb[0], bb[1]);
                mma16816(c1[np * 2 + 1], a, bb[2], bb[3]);
            }
        }

        // ---- epilogue 1 (regs): +Aq, silu -> GEMM2 A-fragments ----
        uint32_t a2[8][4];
        {
            const int qrow = pass * 2 + (wid >> 2);
            #pragma unroll
            for (int kt = 0; kt < 8; kt++) {
                #pragma unroll
                for (int hnt = 0; hnt < 2; hnt++) {
                    const int nt = kt * 2 + hnt;
                    const int f  = nt * 8 + tig * 2;
                    const float aq0 = sAQ[qrow * 128 + f];
                    const float aq1 = sAQ[qrow * 128 + f + 1];
                    const float v0 = silu_f(c1[nt][0] + aq0);
                    const float v1 = silu_f(c1[nt][1] + aq1);
                    const float v2 = silu_f(c1[nt][2] + aq0);
                    const float v3 = silu_f(c1[nt][3] + aq1);
                    a2[kt][hnt * 2 + 0] = pack2(v0, v1);
                    a2[kt][hnt * 2 + 1] = pack2(v2, v3);
                }
            }
        }

        // ---- GEMM2: D2[16x64] = H[16x128] @ W2 (A from registers) ----
        float c2[8][4];
        #pragma unroll
        for (int nt = 0; nt < 8; nt++)
            #pragma unroll
            for (int j = 0; j < 4; j++) c2[nt][j] = 0.f;

        #pragma unroll
        for (int ks = 0; ks < 8; ks++) {
            #pragma unroll
            for (int np = 0; np < 4; np++) {
                uint32_t bb[4];
                ldmx4(bb, sW2b + (np * 16 + brow) * 272 + ks * 32 + bkof);
                mma16816(c2[np * 2 + 0], a2[ks], bb[0], bb[1]);
                mma16816(c2[np * 2 + 1], a2[ks], bb[2], bb[3]);
            }
        }

        // ---- epilogue 2: +b2, store ----
        {
            const int q = q0 + pass * 2 + (wid >> 2);
            const int kbase = k0 + (wid & 3) * 16 + grp;
            #pragma unroll
            for (int h = 0; h < 2; h++) {
                const size_t base = ((size_t)(b * NQ_ + q) * NK_ + kbase + h * 8) * 64;
                #pragma unroll
                for (int nt = 0; nt < 8; nt++) {
                    const int f = nt * 8 + tig * 2;
                    float2 v;
                    v.x = c2[nt][h * 2 + 0] + sB2[f];
                    v.y = c2[nt][h * 2 + 1] + sB2[f + 1];
                    *(float2*)&out[base + f] = v;
                }
            }
        }
        __syncthreads();   // F reads done chip-wide before next pass overwrites
    }
}

// =====================================================================
extern "C" void kernel_launch(void* const* d_in, const int* in_sizes, int n_in,
                              void* d_out, int out_size)
{
    (void)in_sizes; (void)n_in; (void)out_size;
    const float* q_equi = (const float*)d_in[0];
    const float* q_inv  = (const float*)d_in[1];
    const float* k_equi = (const float*)d_in[2];
    const float* k_inv  = (const float*)d_in[3];
    const float* Wqi = (const float*)d_in[4];  const float* bqi = (const float*)d_in[5];
    const float* Wki = (const float*)d_in[6];  const float* bki = (const float*)d_in[7];
    const float* Wqe = (const float*)d_in[8];  const float* bqe = (const float*)d_in[9];
    const float* Wke = (const float*)d_in[10]; const float* bke = (const float*)d_in[11];
    const float* W1  = (const float*)d_in[12]; const float* b1  = (const float*)d_in[13];
    const float* W2  = (const float*)d_in[14]; const float* b2  = (const float*)d_in[15];
    float* out = (float*)d_out;

    cudaFuncSetAttribute(pair_kernel, cudaFuncAttributeMaxDynamicSharedMemorySize, SMEM_TOTAL);

    prep_kernel<<<43, 256>>>(W1, W2);
    proj_kernel<<<dim3(B_ * NQ_, 2), 128>>>(q_equi, q_inv, k_equi, k_inv,
                                            Wqi, bqi, Wki, bki,
                                            Wqe, bqe, Wke, bke, W1, b1);
    pair_kernel<<<dim3(NK_ / 64, NQ_ / 8, B_), 256, SMEM_TOTAL>>>(b2, out);
}

// round 7
// speedup vs baseline: 4.1207x; 1.0359x over previous
#include <cuda_runtime.h>
#include <cuda_fp16.h>
#include <stdint.h>
#include <stddef.h>

// ---------------- problem constants ----------------
#define B_    2
#define NQ_   768
#define NK_   768

// ---------------- static scratch ----------------
__device__ float    g_qe [B_*NQ_*96];       // [b,q, c*32+m]
__device__ float    g_ke [B_*NK_*96];
__device__ float    g_Aq [B_*NQ_*128];      // b1 + qi @ W1[0:32]
__device__ uint32_t g_kih[B_*NK_*16];       // [b,k][16] packed fp16 ki (32 vals)
__device__ uint32_t g_W1h[128*52];          // [n][kq] B-tile for A=[dot|dist|ki] (K=96)
__device__ uint32_t g_W2h[64*68];           // [n][kq] half2{W2[2kq][n], W2[2kq+1][n]}

// ---------------- helpers ----------------
__device__ __forceinline__ uint32_t smem_u32(const void* p){
    uint32_t a;
    asm("{ .reg .u64 t; cvta.to.shared.u64 t, %1; cvt.u32.u64 %0, t; }" : "=r"(a) : "l"(p));
    return a;
}
__device__ __forceinline__ float tanh_ap(float x){
    float y; asm("tanh.approx.f32 %0, %1;" : "=f"(y) : "f"(x)); return y;
}
__device__ __forceinline__ float silu_f(float v){
    const float hv = 0.5f * v;
    return fmaf(hv, tanh_ap(hv), hv);          // v * sigmoid(v)
}
__device__ __forceinline__ uint32_t pack2(float a, float b){
    __half2 h = __floats2half2_rn(a, b);
    return *(const uint32_t*)&h;
}
__device__ __forceinline__ void ldmx4(uint32_t* r, uint32_t addr){
    asm volatile("ldmatrix.sync.aligned.m8n8.x4.shared.b16 {%0,%1,%2,%3}, [%4];"
        : "=r"(r[0]), "=r"(r[1]), "=r"(r[2]), "=r"(r[3]) : "r"(addr));
}
__device__ __forceinline__ void mma16816(float* d, const uint32_t* a, uint32_t b0, uint32_t b1){
    asm volatile(
        "mma.sync.aligned.m16n8k16.row.col.f32.f16.f16.f32 "
        "{%0,%1,%2,%3}, {%4,%5,%6,%7}, {%8,%9}, {%0,%1,%2,%3};"
        : "+f"(d[0]), "+f"(d[1]), "+f"(d[2]), "+f"(d[3])
        : "r"(a[0]), "r"(a[1]), "r"(a[2]), "r"(a[3]), "r"(b0), "r"(b1));
}

// ---------------- smem layout (bytes) ----------------
// fp16 tiles: row stride = odd multiple of 16B -> conflict-free ldmatrix.
#define O_W1H 0                 // [128 n][104 k] fp16, stride 208B  = 26624
#define O_W2H 26624             // [ 64 n][136 k] fp16, stride 272B  = 17408
#define O_F   44032             // [128 p][104 k] fp16, stride 208B  = 26624
#define O_KE  70656             // [64][96] fp32 packed              = 24576
#define O_AQ  95232             // [16][128] fp32                    = 8192
#define O_QE  103424            // [16][96] fp32                     = 6144
#define O_B2  109568            // [64] fp32                         = 256
#define SMEM_TOTAL 109824

// =====================================================================
// Kernel P: per-row projections (side 0/1) + weight prep (side 2).
//   grid = (1536, 3), 128 threads.
// =====================================================================
__global__ __launch_bounds__(128)
void proj_kernel(const float* __restrict__ q_equi, const float* __restrict__ q_inv,
                 const float* __restrict__ k_equi, const float* __restrict__ k_inv,
                 const float* __restrict__ Wqi, const float* __restrict__ bqi,
                 const float* __restrict__ Wki, const float* __restrict__ bki,
                 const float* __restrict__ Wqe, const float* __restrict__ bqe,
                 const float* __restrict__ Wke, const float* __restrict__ bke,
                 const float* __restrict__ W1,  const float* __restrict__ b1,
                 const float* __restrict__ W2)
{
    const int side = blockIdx.y;
    const int r    = blockIdx.x;           // b*768 + n  (sides 0/1)
    const int tid  = threadIdx.x;

    if (side == 2) {
        // -------- weight prep: W1h (K=96 A-order [dot|dist|ki]) + W2h --------
        const int idx = r * 128 + tid;
        if (idx < 128*52) {
            const int n = idx / 52, kq = idx % 52;
            float a = 0.f, b = 0.f;
            if (kq < 48) {
                const int a0 = 2*kq, a1 = 2*kq + 1;
                const int r0 = (a0 < 64) ? (64 + a0) : (a0 - 32);
                const int r1 = (a1 < 64) ? (64 + a1) : (a1 - 32);
                a = W1[(size_t)r0 * 128 + n];
                b = W1[(size_t)r1 * 128 + n];
            }
            g_W1h[n*52 + kq] = pack2(a, b);
        } else if (idx < 128*52 + 64*68) {
            const int j = idx - 128*52;
            const int n = j / 68, kq = j % 68;
            float a = 0.f, b = 0.f;
            if (kq < 64) {
                a = W2[(size_t)(2*kq    ) * 64 + n];
                b = W2[(size_t)(2*kq + 1) * 64 + n];
            }
            g_W2h[n*68 + kq] = pack2(a, b);
        }
        return;
    }

    const float* xe = side ? k_equi : q_equi;
    const float* xi = side ? k_inv  : q_inv;
    const float* We = side ? Wke : Wqe;
    const float* be = side ? bke : bqe;
    const float* Wi = side ? Wki : Wqi;
    const float* bi = side ? bki : bqi;
    float* oute = side ? g_ke : g_qe;

    __shared__ float sxe[768];
    __shared__ float sxi[256];
    __shared__ float spi[32];

    for (int i = tid; i < 768; i += 128) sxe[i] = xe[(size_t)r * 768 + i];
    for (int i = tid; i < 256; i += 128) sxi[i] = xi[(size_t)r * 256 + i];
    __syncthreads();

    if (tid < 96) {
        const int c = tid >> 5, m = tid & 31;
        float acc = be[m];
        #pragma unroll 4
        for (int d = 0; d < 256; d++)
            acc = fmaf(sxe[c * 256 + d], We[d * 32 + m], acc);
        oute[(size_t)r * 96 + c * 32 + m] = acc;
    } else {
        const int m = tid - 96;
        float acc = bi[m];
        #pragma unroll 4
        for (int d = 0; d < 256; d++)
            acc = fmaf(sxi[d], Wi[d * 32 + m], acc);
        spi[m] = acc;
    }
    __syncthreads();

    if (side) {
        if (tid < 16)
            g_kih[(size_t)r * 16 + tid] = pack2(spi[2*tid], spi[2*tid + 1]);
    } else {
        float acc = b1[tid];
        #pragma unroll
        for (int m = 0; m < 32; m++)
            acc = fmaf(spi[m], W1[m * 128 + tid], acc);
        g_Aq[(size_t)r * 128 + tid] = acc;
    }
}

// =====================================================================
// Kernel B: pairwise kernel.
//   CTA = 16 q-rows x 64 k-rows; 8 passes of (2q x 64k, M=128).
//   GEMM1: A=[dot|dist|ki] (K=96) @ W1h ; epi: +Aq, silu (regs) ; GEMM2 (K=128)
// =====================================================================
__global__ __launch_bounds__(256, 2)
void pair_kernel(const float* __restrict__ b2g, float* __restrict__ out)
{
    extern __shared__ char sm[];
    __half*   sW1h = (__half*)(sm + O_W1H);
    __half*   sW2h = (__half*)(sm + O_W2H);
    __half*   sF   = (__half*)(sm + O_F);
    uint32_t* sFu  = (uint32_t*)(sm + O_F);
    float*    sKE  = (float*)(sm + O_KE);
    float*    sAQ  = (float*)(sm + O_AQ);
    float*    sQE  = (float*)(sm + O_QE);
    float*    sB2  = (float*)(sm + O_B2);

    const int tid = threadIdx.x;
    const int b   = blockIdx.z;
    const int k0  = blockIdx.x * 64;
    const int q0  = blockIdx.y * 16;

    // ---------------- phase 0: one-time loads ----------------
    {   // pre-packed fp16 weights: W1h 1664 f4, W2h 1088 f4
        float4* d1 = (float4*)sW1h; const float4* s1 = (const float4*)g_W1h;
        for (int i = tid; i < 1664; i += 256) d1[i] = s1[i];
        float4* d2 = (float4*)sW2h; const float4* s2 = (const float4*)g_W2h;
        for (int i = tid; i < 1088; i += 256) d2[i] = s2[i];
    }
    {   // ke: packed 96-float rows (1536 f4)
        const float4* src = (const float4*)(g_ke + (size_t)(b * NK_ + k0) * 96);
        float4* dst = (float4*)sKE;
        for (int i = tid; i < 1536; i += 256) dst[i] = src[i];
    }
    {   // ki -> F cols 64..95 (uint32 cols 32..47), rows kk and 64+kk
        for (int i = tid; i < 1024; i += 256) {
            const int kk = i >> 4, c = i & 15;
            const uint32_t v = g_kih[(size_t)(b * NK_ + k0 + kk) * 16 + c];
            sFu[kk * 52 + 32 + c]        = v;
            sFu[(64 + kk) * 52 + 32 + c] = v;
        }
    }
    {   // qe: 16 rows = 384 f4 ; Aq: 16 rows = 512 f4
        for (int i = tid; i < 384; i += 256)
            ((float4*)sQE)[i] = *(const float4*)(g_qe + (size_t)(b * NQ_ + q0) * 96 + i * 4);
        for (int i = tid; i < 512; i += 256)
            ((float4*)sAQ)[i] = *(const float4*)(g_Aq + (size_t)(b * NQ_ + q0) * 128 + i * 4);
        if (tid >= 192 && tid < 256) sB2[tid - 192] = b2g[tid - 192];
    }
    __syncthreads();

    // ---------------- warp/lane geometry ----------------
    const int wid = tid >> 5, lane = tid & 31;
    const int grp = lane >> 2, tig = lane & 3;
    const int mb  = wid * 16;                  // warp M-tile rows

    const uint32_t sFb  = smem_u32(sF);
    const uint32_t sW1b = smem_u32(sW1h);
    const uint32_t sW2b = smem_u32(sW2h);

    const int arow = lane & 15;
    const int akof = (lane >> 4) * 16;
    const int brow = (lane & 7) + ((lane >> 4) << 3);
    const int bkof = ((lane >> 3) & 1) * 16;

    // ---------------- pass loop: 8 x (2q x 64k) ----------------
    #pragma unroll 1
    for (int pass = 0; pass < 8; pass++) {
        // ---- feats: dot + dist -> F cols 0..63 (fp16) ----
        #pragma unroll
        for (int it = 0; it < 4; it++) {
            const int g  = tid + it * 256;
            const int p  = g >> 3;             // pair 0..127
            const int m  = (g & 7) * 4;
            const int qq = pass * 2 + (p >> 6), kk = p & 63;
            float4 dot = make_float4(0.f, 0.f, 0.f, 0.f);
            float4 d2  = make_float4(0.f, 0.f, 0.f, 0.f);
            #pragma unroll
            for (int c = 0; c < 3; c++) {
                const float4 a  = *(const float4*)&sQE[qq * 96 + c * 32 + m];
                const float4 bb = *(const float4*)&sKE[kk * 96 + c * 32 + m];
                dot.x = fmaf(a.x, bb.x, dot.x);
                dot.y = fmaf(a.y, bb.y, dot.y);
                dot.z = fmaf(a.z, bb.z, dot.z);
                dot.w = fmaf(a.w, bb.w, dot.w);
                float dx = a.x - bb.x; d2.x = fmaf(dx, dx, d2.x);
                float dy = a.y - bb.y; d2.y = fmaf(dy, dy, d2.y);
                float dz = a.z - bb.z; d2.z = fmaf(dz, dz, d2.z);
                float dw = a.w - bb.w; d2.w = fmaf(dw, dw, d2.w);
            }
            *(__half2*)(sF + p * 104 + m)          = __floats2half2_rn(dot.x, dot.y);
            *(__half2*)(sF + p * 104 + m + 2)      = __floats2half2_rn(dot.z, dot.w);
            *(__half2*)(sF + p * 104 + 32 + m)     = __floats2half2_rn(sqrtf(d2.x), sqrtf(d2.y));
            *(__half2*)(sF + p * 104 + 32 + m + 2) = __floats2half2_rn(sqrtf(d2.z), sqrtf(d2.w));
        }
        __syncthreads();

        // ---- GEMM1: D1[16x128] = F[16x96] @ W1h ----
        float c1[16][4];
        #pragma unroll
        for (int nt = 0; nt < 16; nt++)
            #pragma unroll
            for (int j = 0; j < 4; j++) c1[nt][j] = 0.f;

        #pragma unroll
        for (int ks = 0; ks < 6; ks++) {
            uint32_t a[4];
            ldmx4(a, sFb + (mb + arow) * 208 + ks * 32 + akof);
            #pragma unroll
            for (int np = 0; np < 8; np++) {
                uint32_t bb[4];
                ldmx4(bb, sW1b + (np * 16 + brow) * 208 + ks * 32 + bkof);
                mma16816(c1[np * 2 + 0], a, bb[0], bb[1]);
                mma16816(c1[np * 2 + 1], a, bb[2], bb[3]);
            }
        }

        // ---- epilogue 1 (regs): +Aq, silu -> GEMM2 A-fragments ----
        uint32_t a2[8][4];
        {
            const int qrow = pass * 2 + (wid >> 2);
            #pragma unroll
            for (int kt = 0; kt < 8; kt++) {
                #pragma unroll
                for (int hnt = 0; hnt < 2; hnt++) {
                    const int nt = kt * 2 + hnt;
                    const int f  = nt * 8 + tig * 2;
                    const float aq0 = sAQ[qrow * 128 + f];
                    const float aq1 = sAQ[qrow * 128 + f + 1];
                    const float v0 = silu_f(c1[nt][0] + aq0);
                    const float v1 = silu_f(c1[nt][1] + aq1);
                    const float v2 = silu_f(c1[nt][2] + aq0);
                    const float v3 = silu_f(c1[nt][3] + aq1);
                    a2[kt][hnt * 2 + 0] = pack2(v0, v1);
                    a2[kt][hnt * 2 + 1] = pack2(v2, v3);
                }
            }
        }

        // ---- GEMM2: D2[16x64] = H[16x128] @ W2 (A from registers) ----
        float c2[8][4];
        #pragma unroll
        for (int nt = 0; nt < 8; nt++)
            #pragma unroll
            for (int j = 0; j < 4; j++) c2[nt][j] = 0.f;

        #pragma unroll
        for (int ks = 0; ks < 8; ks++) {
            #pragma unroll
            for (int np = 0; np < 4; np++) {
                uint32_t bb[4];
                ldmx4(bb, sW2b + (np * 16 + brow) * 272 + ks * 32 + bkof);
                mma16816(c2[np * 2 + 0], a2[ks], bb[0], bb[1]);
                mma16816(c2[np * 2 + 1], a2[ks], bb[2], bb[3]);
            }
        }

        // ---- epilogue 2: +b2, store ----
        {
            const int q = q0 + pass * 2 + (wid >> 2);
            const int kbase = k0 + (wid & 3) * 16 + grp;
            #pragma unroll
            for (int h = 0; h < 2; h++) {
                const size_t base = ((size_t)(b * NQ_ + q) * NK_ + kbase + h * 8) * 64;
                #pragma unroll
                for (int nt = 0; nt < 8; nt++) {
                    const int f = nt * 8 + tig * 2;
                    float2 v;
                    v.x = c2[nt][h * 2 + 0] + sB2[f];
                    v.y = c2[nt][h * 2 + 1] + sB2[f + 1];
                    *(float2*)&out[base + f] = v;
                }
            }
        }
        __syncthreads();   // F reads done CTA-wide before next pass overwrites
    }
}

// =====================================================================
extern "C" void kernel_launch(void* const* d_in, const int* in_sizes, int n_in,
                              void* d_out, int out_size)
{
    (void)in_sizes; (void)n_in; (void)out_size;
    const float* q_equi = (const float*)d_in[0];
    const float* q_inv  = (const float*)d_in[1];
    const float* k_equi = (const float*)d_in[2];
    const float* k_inv  = (const float*)d_in[3];
    const float* Wqi = (const float*)d_in[4];  const float* bqi = (const float*)d_in[5];
    const float* Wki = (const float*)d_in[6];  const float* bki = (const float*)d_in[7];
    const float* Wqe = (const float*)d_in[8];  const float* bqe = (const float*)d_in[9];
    const float* Wke = (const float*)d_in[10]; const float* bke = (const float*)d_in[11];
    const float* W1  = (const float*)d_in[12]; const float* b1  = (const float*)d_in[13];
    const float* W2  = (const float*)d_in[14]; const float* b2  = (const float*)d_in[15];
    float* out = (float*)d_out;

    cudaFuncSetAttribute(pair_kernel, cudaFuncAttributeMaxDynamicSharedMemorySize, SMEM_TOTAL);

    proj_kernel<<<dim3(B_ * NQ_, 3), 128>>>(q_equi, q_inv, k_equi, k_inv,
                                            Wqi, bqi, Wki, bki,
                                            Wqe, bqe, Wke, bke, W1, b1, W2);
    pair_kernel<<<dim3(NK_ / 64, NQ_ / 16, B_), 256, SMEM_TOTAL>>>(b2, out);
}